// round 2
// baseline (speedup 1.0000x reference)
#include <cuda_runtime.h>
#include <cuda_bf16.h>
#include <cstdint>
#include <math.h>

// ============================================================================
// InfoNCE loss, GB300 (sm_103a, PTX target sm_103 -> legacy mma.sync path)
//  loss = -log(P / (P + N)),
//  P = sum(exp(zi.ziT / T))  [symmetric: off-diag tiles weighted x2]
//  N = sum(exp(zi.zjT / T))
//
//  1) norm_kernel: L2-normalize rows, cast to bf16 -> g_zi, g_zj
//  2) gemm_kernel: 128x128 tile bf16 HMMA (mma.sync m16n8k16), cp.async
//     double-buffered K pipeline, fused exp-sum epilogue in registers
//  3) finish_kernel: reduce partials -> scalar loss
// ============================================================================

#define N_ROWS   8192
#define DDIM     512
#define BM       128
#define BN       128
#define BK       64
#define NKCH     (DDIM / BK)        // 8
#define NTHREADS 256

#define ROW_TILES 64                 // 8192 / 128
#define NEG_TILES (ROW_TILES * ROW_TILES)   // 4096
#define DIAG_TILES ROW_TILES                // 64
#define UPPER_TILES (ROW_TILES * (ROW_TILES - 1) / 2)  // 2016
#define TOTAL_TILES (NEG_TILES + DIAG_TILES + UPPER_TILES) // 6176

// exp(x/T) = ex2(x * (1/T) * log2(e)), T = 0.1
#define EXP_SCALE 14.4269504088896340736f

__device__ __nv_bfloat16 g_zi[(size_t)N_ROWS * DDIM];
__device__ __nv_bfloat16 g_zj[(size_t)N_ROWS * DDIM];
__device__ double g_partials[TOTAL_TILES];

// ---------------------------------------------------------------------------
__device__ __forceinline__ uint32_t smem_u32(const void* p) {
    uint32_t a;
    asm("{ .reg .u64 t; cvta.to.shared.u64 t, %1; cvt.u32.u64 %0, t; }" : "=r"(a) : "l"(p));
    return a;
}

#define CP_ASYNC16(dst_u32, src_ptr) \
    asm volatile("cp.async.cg.shared.global [%0], [%1], 16;" \
                 :: "r"(dst_u32), "l"(src_ptr) : "memory")
#define CP_COMMIT() asm volatile("cp.async.commit_group;" ::: "memory")
#define CP_WAIT(n)  asm volatile("cp.async.wait_group %0;" :: "n"(n) : "memory")

__device__ __forceinline__ void ldmx4(uint32_t* r, uint32_t addr) {
    asm volatile("ldmatrix.sync.aligned.m8n8.x4.shared.b16 {%0,%1,%2,%3}, [%4];"
                 : "=r"(r[0]), "=r"(r[1]), "=r"(r[2]), "=r"(r[3]) : "r"(addr));
}

__device__ __forceinline__ void mma16816(float* d, const uint32_t* a,
                                         const uint32_t* b) {
    asm volatile(
        "mma.sync.aligned.m16n8k16.row.col.f32.bf16.bf16.f32 "
        "{%0,%1,%2,%3}, {%4,%5,%6,%7}, {%8,%9}, {%0,%1,%2,%3};"
        : "+f"(d[0]), "+f"(d[1]), "+f"(d[2]), "+f"(d[3])
        : "r"(a[0]), "r"(a[1]), "r"(a[2]), "r"(a[3]), "r"(b[0]), "r"(b[1]));
}

// SW128 swizzle specialized for 128B rows: off = row*128 + colb (colb < 128)
// swizzled colb = colb ^ ((row & 7) << 4)
// smem buffers: A[buf] at buf*32768, B[buf] at buf*32768 + 16384; rows of 128B.
#define SMEM_BUF_STRIDE 32768
#define SMEM_B_OFF      16384
#define SMEM_DYN_TOTAL  (2 * SMEM_BUF_STRIDE)   // 65536

// ---------------------------------------------------------------------------
// 1) normalize + bf16 cast.  One block per row (16384 rows), 128 threads.
// ---------------------------------------------------------------------------
__global__ void __launch_bounds__(128) norm_kernel(const float* __restrict__ zi,
                                                   const float* __restrict__ zj) {
    int row = blockIdx.x;
    const float* src = (row < N_ROWS) ? (zi + (size_t)row * DDIM)
                                      : (zj + (size_t)(row - N_ROWS) * DDIM);
    __nv_bfloat16* dst = (row < N_ROWS) ? (g_zi + (size_t)row * DDIM)
                                        : (g_zj + (size_t)(row - N_ROWS) * DDIM);
    int t = threadIdx.x;
    float4 v = ((const float4*)src)[t];
    float ss = v.x * v.x + v.y * v.y + v.z * v.z + v.w * v.w;
    #pragma unroll
    for (int o = 16; o; o >>= 1) ss += __shfl_xor_sync(0xFFFFFFFFu, ss, o);
    __shared__ float ws[4];
    if ((t & 31) == 0) ws[t >> 5] = ss;
    __syncthreads();
    float tot = ws[0] + ws[1] + ws[2] + ws[3];
    float inv = 1.0f / fmaxf(sqrtf(tot), 1e-12f);

    __nv_bfloat162 p0 = __floats2bfloat162_rn(v.x * inv, v.y * inv);
    __nv_bfloat162 p1 = __floats2bfloat162_rn(v.z * inv, v.w * inv);
    uint2 pack;
    pack.x = *reinterpret_cast<uint32_t*>(&p0);
    pack.y = *reinterpret_cast<uint32_t*>(&p1);
    ((uint2*)dst)[t] = pack;
}

// ---------------------------------------------------------------------------
// 2) fused GEMM + exp-sum.
//    Block computes one 128x128 tile of C = A @ B^T (A,B rows of bf16, K=512).
//    8 warps as 4 (M) x 2 (N): warp tile 32x64 -> 2 mtiles x 8 ntiles of
//    m16n8k16, 64 fp32 accum regs per thread.
// ---------------------------------------------------------------------------
__global__ void __launch_bounds__(NTHREADS, 2) gemm_kernel() {
    extern __shared__ char smem[];
    uint32_t sb = smem_u32(smem);
    int tid  = threadIdx.x;
    int lane = tid & 31;
    int wid  = tid >> 5;
    int warp_m = wid & 3;    // 0..3 -> 32-row slab
    int warp_n = wid >> 2;   // 0..1 -> 64-col slab

    // ---- tile decode: neg / pos-diag / pos-upper(x2) ----
    int b = blockIdx.x;
    int rt, ct, weight;
    const __nv_bfloat16* Bmat;
    if (b < NEG_TILES) {
        rt = b >> 6; ct = b & 63; weight = 1; Bmat = g_zj;
    } else if (b < NEG_TILES + DIAG_TILES) {
        rt = ct = b - NEG_TILES; weight = 1; Bmat = g_zi;
    } else {
        int k = b - NEG_TILES - DIAG_TILES;   // 0..2015
        int r = 0, rowlen = ROW_TILES - 1;
        while (k >= rowlen) { k -= rowlen; rowlen--; r++; }
        rt = r; ct = r + 1 + k; weight = 2; Bmat = g_zi;
    }
    const __nv_bfloat16* Asrc = g_zi + (size_t)rt * BM * DDIM;
    const __nv_bfloat16* Bsrc = Bmat + (size_t)ct * BN * DDIM;

    // ---- accumulators ----
    float acc[2][8][4];
    #pragma unroll
    for (int mt = 0; mt < 2; mt++)
        #pragma unroll
        for (int nt = 0; nt < 8; nt++)
            #pragma unroll
            for (int i = 0; i < 4; i++) acc[mt][nt][i] = 0.0f;

    // ---- per-thread staging coords (8 x 16B chunks per buffer) ----
    // chunk i in [0,1024): r = i>>3 (row), s = i&7 (16B seg within 128B row)
    // thread handles i = tid + 256*j, j in [0,4) for A and same for B.
    // ---- ldmatrix per-thread address components ----
    int a_row0 = warp_m * 32 + (lane & 15);
    int a_row1 = a_row0 + 16;
    uint32_t a_rb0 = a_row0 * 128, a_xm0 = (a_row0 & 7) << 4;
    uint32_t a_rb1 = a_row1 * 128, a_xm1 = (a_row1 & 7) << 4;
    uint32_t a_csub = (lane >> 4) << 4;   // byte offset within k16 (0 or 16)

    uint32_t b_rb[4], b_xm[4];
    #pragma unroll
    for (int ntp = 0; ntp < 4; ntp++) {
        int rb = warp_n * 64 + ntp * 16 + ((lane >> 4) << 3) + (lane & 7);
        b_rb[ntp] = rb * 128;
        b_xm[ntp] = (rb & 7) << 4;
    }
    uint32_t b_csub = ((lane >> 3) & 1) << 4;  // 0 or 16 bytes

    // ---- staging lambda-ish macro ----
    #define STAGE(buf, kc) do {                                                 \
        uint32_t abase = sb + (buf) * SMEM_BUF_STRIDE;                          \
        uint32_t bbase = abase + SMEM_B_OFF;                                    \
        const char* agp = (const char*)(Asrc) + (size_t)(kc) * BK * 2;          \
        const char* bgp = (const char*)(Bsrc) + (size_t)(kc) * BK * 2;          \
        _Pragma("unroll")                                                       \
        for (int j = 0; j < 4; j++) {                                           \
            int i = tid + j * NTHREADS;                                         \
            int r = i >> 3, s = i & 7;                                          \
            uint32_t dst = abase + r * 128 + ((s * 16) ^ ((r & 7) << 4));       \
            CP_ASYNC16(dst, agp + (size_t)r * (DDIM * 2) + s * 16);             \
        }                                                                       \
        _Pragma("unroll")                                                       \
        for (int j = 0; j < 4; j++) {                                           \
            int i = tid + j * NTHREADS;                                         \
            int r = i >> 3, s = i & 7;                                          \
            uint32_t dst = bbase + r * 128 + ((s * 16) ^ ((r & 7) << 4));       \
            CP_ASYNC16(dst, bgp + (size_t)r * (DDIM * 2) + s * 16);             \
        }                                                                       \
    } while (0)

    STAGE(0, 0);
    CP_COMMIT();

    for (int kc = 0; kc < NKCH; kc++) {
        int cur = kc & 1;
        if (kc + 1 < NKCH) {
            STAGE(1 - cur, kc + 1);
            CP_COMMIT();
            CP_WAIT(1);
        } else {
            CP_WAIT(0);
        }
        __syncthreads();

        uint32_t abase = sb + cur * SMEM_BUF_STRIDE;
        uint32_t bbase = abase + SMEM_B_OFF;

        #pragma unroll
        for (int kk = 0; kk < 4; kk++) {          // 4 k16 steps in BK=64
            uint32_t kb = kk * 32;                // byte col offset of k16 step
            uint32_t afr[2][4];
            ldmx4(afr[0], abase + a_rb0 + ((kb + a_csub) ^ a_xm0));
            ldmx4(afr[1], abase + a_rb1 + ((kb + a_csub) ^ a_xm1));
            uint32_t bfr[8][2];
            #pragma unroll
            for (int ntp = 0; ntp < 4; ntp++) {
                uint32_t r[4];
                ldmx4(r, bbase + b_rb[ntp] + ((kb + b_csub) ^ b_xm[ntp]));
                bfr[2 * ntp][0] = r[0]; bfr[2 * ntp][1] = r[1];
                bfr[2 * ntp + 1][0] = r[2]; bfr[2 * ntp + 1][1] = r[3];
            }
            #pragma unroll
            for (int mt = 0; mt < 2; mt++)
                #pragma unroll
                for (int nt = 0; nt < 8; nt++)
                    mma16816(acc[mt][nt], afr[mt], bfr[nt]);
        }
        __syncthreads();
    }

    // ---- epilogue: exp-sum of all 64 accum values ----
    float psum = 0.0f;
    #pragma unroll
    for (int mt = 0; mt < 2; mt++)
        #pragma unroll
        for (int nt = 0; nt < 8; nt++)
            #pragma unroll
            for (int i = 0; i < 4; i++) {
                float s = acc[mt][nt][i] * EXP_SCALE;
                float e;
                asm("ex2.approx.ftz.f32 %0, %1;" : "=f"(e) : "f"(s));
                psum += e;
            }
    #pragma unroll
    for (int o = 16; o; o >>= 1) psum += __shfl_xor_sync(0xFFFFFFFFu, psum, o);

    __shared__ float red[8];
    if (lane == 0) red[wid] = psum;
    __syncthreads();
    if (tid == 0) {
        double tot = 0.0;
        #pragma unroll
        for (int w = 0; w < 8; w++) tot += (double)red[w];
        g_partials[blockIdx.x] = tot * (double)weight;
    }
}

// ---------------------------------------------------------------------------
// 3) final reduction -> loss scalar
// ---------------------------------------------------------------------------
__global__ void __launch_bounds__(256) finish_kernel(float* __restrict__ out) {
    int t = threadIdx.x;
    double p = 0.0, n = 0.0;
    for (int i = t; i < TOTAL_TILES; i += 256) {
        double v = g_partials[i];
        if (i < NEG_TILES) n += v; else p += v;
    }
    __shared__ double sp[256], sn[256];
    sp[t] = p; sn[t] = n;
    __syncthreads();
    for (int s = 128; s; s >>= 1) {
        if (t < s) { sp[t] += sp[t + s]; sn[t] += sn[t + s]; }
        __syncthreads();
    }
    if (t == 0) {
        double P = sp[0], N = sn[0];
        out[0] = (float)(-log(P / (N + P)));
    }
}

// ---------------------------------------------------------------------------
extern "C" void kernel_launch(void* const* d_in, const int* in_sizes, int n_in,
                              void* d_out, int out_size) {
    const float* zi = (const float*)d_in[0];
    const float* zj = (const float*)d_in[1];

    cudaFuncSetAttribute(gemm_kernel, cudaFuncAttributeMaxDynamicSharedMemorySize,
                         SMEM_DYN_TOTAL);

    norm_kernel<<<2 * N_ROWS, 128>>>(zi, zj);
    gemm_kernel<<<TOTAL_TILES, NTHREADS, SMEM_DYN_TOTAL>>>();
    finish_kernel<<<1, 256>>>((float*)d_out);
}